// round 3
// baseline (speedup 1.0000x reference)
#include <cuda_runtime.h>

#define TOKENS   16384
#define KDIM     8192
#define MTILE    64
#define NTHREADS 128
#define KSTAGE   64
#define NSTAGES  (KDIM / KSTAGE)   /* 128 */
#define NBUF     4
#define XSTRIDE  68                /* floats; 68 % 32 == 4 -> conflict-free frags */
#define WSTRIDE  68
#define NOUT     24

#define XS_FLOATS (MTILE * XSTRIDE)          /* 4352 */
#define WS_FLOATS (NOUT * WSTRIDE)           /* 1632 */
#define SMEM_BYTES (NBUF * (XS_FLOATS + WS_FLOATS) * 4)  /* 95744 */

__device__ __forceinline__ void mma_tf32(float c[4],
                                         unsigned a0, unsigned a1, unsigned a2, unsigned a3,
                                         unsigned b0, unsigned b1) {
    asm volatile(
        "mma.sync.aligned.m16n8k8.row.col.f32.tf32.tf32.f32 "
        "{%0,%1,%2,%3}, {%4,%5,%6,%7}, {%8,%9}, {%0,%1,%2,%3};\n"
        : "+f"(c[0]), "+f"(c[1]), "+f"(c[2]), "+f"(c[3])
        : "r"(a0), "r"(a1), "r"(a2), "r"(a3), "r"(b0), "r"(b1));
}

__device__ __forceinline__ void cp_async16(void* smem_dst, const void* gsrc) {
    unsigned dst = (unsigned)__cvta_generic_to_shared(smem_dst);
    asm volatile("cp.async.cg.shared.global [%0], [%1], 16;\n" :: "r"(dst), "l"(gsrc));
}

__global__ void __launch_bounds__(NTHREADS)
mhc_kernel(const float* __restrict__ x,
           const float* __restrict__ a_pre_p, const float* __restrict__ a_post_p,
           const float* __restrict__ a_res_p,
           const float* __restrict__ b_pre, const float* __restrict__ b_post,
           const float* __restrict__ b_res,
           const float* __restrict__ W_pre, const float* __restrict__ W_post,
           const float* __restrict__ W_res,
           float* __restrict__ out)
{
    extern __shared__ float smem[];
    float* xs = smem;                          // NBUF * XS_FLOATS
    float* ws = smem + NBUF * XS_FLOATS;       // NBUF * WS_FLOATS

    const int tid  = threadIdx.x;
    const int lane = tid & 31;
    const int warp = tid >> 5;
    const int g    = lane >> 2;   // group id (row within m16 tile)
    const int tig  = lane & 3;    // thread-in-group
    const int tokbase = blockIdx.x * MTILE;

    // ---- staging assignments ----
    const int stok = tid >> 4;          // 0..7 (token rows stok + 8i)
    const int c4   = (tid & 15) * 4;    // float offset within the 64-float stage

    // W rows for this thread: r0, r0+8, r0+16  (combined: 0-3 pre, 4-7 post, 8-23 res)
    const float* wrowp[3];
    {
        int r0 = tid >> 4;
        wrowp[0] = (r0 < 4) ? (W_pre + (size_t)r0 * KDIM) : (W_post + (size_t)(r0 - 4) * KDIM);
        wrowp[1] = W_res + (size_t)(r0)     * KDIM;  // rows 8..15  -> res 0..7
        wrowp[2] = W_res + (size_t)(r0 + 8) * KDIM;  // rows 16..23 -> res 8..15
    }

    const float* xbase = x + (size_t)tokbase * KDIM;

    float acc[3][4];
    #pragma unroll
    for (int n = 0; n < 3; n++)
        #pragma unroll
        for (int j = 0; j < 4; j++) acc[n][j] = 0.f;

    // ---- prologue: issue stages 0..NBUF-2 ----
    #pragma unroll
    for (int ps = 0; ps < NBUF - 1; ps++) {
        const int kb = ps * KSTAGE;
        float* xbuf = xs + ps * XS_FLOATS;
        float* wbuf = ws + ps * WS_FLOATS;
        #pragma unroll
        for (int i = 0; i < 8; i++) {
            int tok = stok + i * 8;
            cp_async16(&xbuf[tok * XSTRIDE + c4], xbase + (size_t)tok * KDIM + kb + c4);
        }
        #pragma unroll
        for (int i = 0; i < 3; i++) {
            int row = (tid >> 4) + i * 8;
            cp_async16(&wbuf[row * WSTRIDE + c4], wrowp[i] + kb + c4);
        }
        asm volatile("cp.async.commit_group;\n");
    }

    #pragma unroll 1
    for (int s = 0; s < NSTAGES; s++) {
        const int buf = s & (NBUF - 1);
        const int ls  = s + NBUF - 1;
        if (ls < NSTAGES) {
            const int kb = ls * KSTAGE;
            const int nb = ls & (NBUF - 1);
            float* xbuf = xs + nb * XS_FLOATS;
            float* wbuf = ws + nb * WS_FLOATS;
            #pragma unroll
            for (int i = 0; i < 8; i++) {
                int tok = stok + i * 8;
                cp_async16(&xbuf[tok * XSTRIDE + c4], xbase + (size_t)tok * KDIM + kb + c4);
            }
            #pragma unroll
            for (int i = 0; i < 3; i++) {
                int row = (tid >> 4) + i * 8;
                cp_async16(&wbuf[row * WSTRIDE + c4], wrowp[i] + kb + c4);
            }
            asm volatile("cp.async.commit_group;\n");
            asm volatile("cp.async.wait_group %0;\n" :: "n"(NBUF - 1));
        } else {
            asm volatile("cp.async.wait_group 0;\n");
        }
        __syncthreads();

        const float* xr0 = xs + buf * XS_FLOATS + (warp * 16 + g) * XSTRIDE + tig;
        const float* xr1 = xr0 + 8 * XSTRIDE;
        const float* wr  = ws + buf * WS_FLOATS + g * WSTRIDE + tig;

        #pragma unroll
        for (int st = 0; st < KSTAGE / 8; st++) {
            unsigned a0 = __float_as_uint(xr0[st * 8]);
            unsigned a2 = __float_as_uint(xr0[st * 8 + 4]);
            unsigned a1 = __float_as_uint(xr1[st * 8]);
            unsigned a3 = __float_as_uint(xr1[st * 8 + 4]);
            #pragma unroll
            for (int nt = 0; nt < 3; nt++) {
                unsigned b0 = __float_as_uint(wr[nt * 8 * WSTRIDE + st * 8]);
                unsigned b1 = __float_as_uint(wr[nt * 8 * WSTRIDE + st * 8 + 4]);
                mma_tf32(acc[nt], a0, a1, a2, a3, b0, b1);
            }
        }
        __syncthreads();
    }

    // ---- epilogue: gather 24 outputs per token into smem, then per-token math ----
    float* accs = smem;   // 64 * 25 floats, reuse staging buffer
    {
        int t0 = warp * 16 + g;
        #pragma unroll
        for (int nt = 0; nt < 3; nt++) {
            int n0 = nt * 8 + tig * 2;
            accs[t0 * 25 + n0]           = acc[nt][0];
            accs[t0 * 25 + n0 + 1]       = acc[nt][1];
            accs[(t0 + 8) * 25 + n0]     = acc[nt][2];
            accs[(t0 + 8) * 25 + n0 + 1] = acc[nt][3];
        }
    }
    __syncthreads();

    if (tid < MTILE) {
        const float ap  = *a_pre_p;
        const float apo = *a_post_p;
        const float ar  = *a_res_p;
        const int gtok = tokbase + tid;

        float h[NOUT];
        #pragma unroll
        for (int o = 0; o < NOUT; o++) h[o] = accs[tid * 25 + o];

        float* out_pre  = out;
        float* out_post = out + (size_t)TOKENS * 4;
        float* out_res  = out + (size_t)TOKENS * 8;

        #pragma unroll
        for (int o = 0; o < 4; o++) {
            float z = ap * h[o] + b_pre[o];
            out_pre[(size_t)gtok * 4 + o] = 1.f / (1.f + __expf(-z));
        }
        #pragma unroll
        for (int o = 0; o < 4; o++) {
            float z = apo * h[4 + o] + b_post[o];
            out_post[(size_t)gtok * 4 + o] = 2.f / (1.f + __expf(-z));
        }

        // Sinkhorn-Knopp, linear domain (== log-domain reference in exact arithmetic)
        float P[16];
        #pragma unroll
        for (int i = 0; i < 16; i++) P[i] = __expf(ar * h[8 + i] + b_res[i]);

        #pragma unroll 1
        for (int it = 0; it < 20; it++) {
            #pragma unroll
            for (int i = 0; i < 4; i++) {
                float srow = P[i*4] + P[i*4+1] + P[i*4+2] + P[i*4+3];
                float r = 1.f / srow;
                P[i*4] *= r; P[i*4+1] *= r; P[i*4+2] *= r; P[i*4+3] *= r;
            }
            #pragma unroll
            for (int j = 0; j < 4; j++) {
                float scol = P[j] + P[4+j] + P[8+j] + P[12+j];
                float r = 1.f / scol;
                P[j] *= r; P[4+j] *= r; P[8+j] *= r; P[12+j] *= r;
            }
        }
        #pragma unroll
        for (int i = 0; i < 16; i++) out_res[(size_t)gtok * 16 + i] = P[i];
    }
}

extern "C" void kernel_launch(void* const* d_in, const int* in_sizes, int n_in,
                              void* d_out, int out_size) {
    const float* x      = (const float*)d_in[0];
    const float* a_pre  = (const float*)d_in[1];
    const float* a_post = (const float*)d_in[2];
    const float* a_res  = (const float*)d_in[3];
    const float* b_pre  = (const float*)d_in[4];
    const float* b_post = (const float*)d_in[5];
    const float* b_res  = (const float*)d_in[6];
    const float* W_pre  = (const float*)d_in[7];
    const float* W_post = (const float*)d_in[8];
    const float* W_res  = (const float*)d_in[9];

    cudaFuncSetAttribute(mhc_kernel, cudaFuncAttributeMaxDynamicSharedMemorySize,
                         SMEM_BYTES);

    mhc_kernel<<<TOKENS / MTILE, NTHREADS, SMEM_BYTES>>>(
        x, a_pre, a_post, a_res, b_pre, b_post, b_res,
        W_pre, W_post, W_res, (float*)d_out);
}

// round 4
// speedup vs baseline: 1.0893x; 1.0893x over previous
#include <cuda_runtime.h>

#define TOKENS   16384
#define KDIM     8192
#define MTILE    64
#define NTHREADS 128
#define KSTAGE   64
#define NSTAGES  (KDIM / KSTAGE)   /* 128 */
#define NBUF     4
#define XSTRIDE  68                /* floats; 68 % 32 == 4 -> conflict-free frags */
#define WSTRIDE  68
#define NOUT     24

#define XS_FLOATS (MTILE * XSTRIDE)          /* 4352 */
#define WS_FLOATS (NOUT * WSTRIDE)           /* 1632 */
#define SMEM_BYTES (NBUF * (XS_FLOATS + WS_FLOATS) * 4)  /* 95744 */

__device__ __forceinline__ void mma_tf32(float c[4],
                                         unsigned a0, unsigned a1, unsigned a2, unsigned a3,
                                         unsigned b0, unsigned b1) {
    asm volatile(
        "mma.sync.aligned.m16n8k8.row.col.f32.tf32.tf32.f32 "
        "{%0,%1,%2,%3}, {%4,%5,%6,%7}, {%8,%9}, {%0,%1,%2,%3};\n"
        : "+f"(c[0]), "+f"(c[1]), "+f"(c[2]), "+f"(c[3])
        : "r"(a0), "r"(a1), "r"(a2), "r"(a3), "r"(b0), "r"(b1));
}

__device__ __forceinline__ void cp_async16(void* smem_dst, const void* gsrc) {
    unsigned dst = (unsigned)__cvta_generic_to_shared(smem_dst);
    asm volatile("cp.async.cg.shared.global [%0], [%1], 16;\n" :: "r"(dst), "l"(gsrc));
}

__global__ void __launch_bounds__(NTHREADS)
mhc_kernel(const float* __restrict__ x,
           const float* __restrict__ a_pre_p, const float* __restrict__ a_post_p,
           const float* __restrict__ a_res_p,
           const float* __restrict__ b_pre, const float* __restrict__ b_post,
           const float* __restrict__ b_res,
           const float* __restrict__ W_pre, const float* __restrict__ W_post,
           const float* __restrict__ W_res,
           float* __restrict__ out)
{
    extern __shared__ float smem[];
    float* xs = smem;                          // NBUF * XS_FLOATS
    float* ws = smem + NBUF * XS_FLOATS;       // NBUF * WS_FLOATS

    const int tid  = threadIdx.x;
    const int lane = tid & 31;
    const int warp = tid >> 5;
    const int g    = lane >> 2;   // group id (row within m16 tile)
    const int tig  = lane & 3;    // thread-in-group
    const int tokbase = blockIdx.x * MTILE;

    // ---- staging assignments ----
    const int stok = tid >> 4;          // 0..7 (token rows stok + 8i)
    const int c4   = (tid & 15) * 4;    // float offset within the 64-float stage

    // W rows for this thread: r0, r0+8, r0+16  (combined: 0-3 pre, 4-7 post, 8-23 res)
    const float* wrowp[3];
    {
        int r0 = tid >> 4;
        wrowp[0] = (r0 < 4) ? (W_pre + (size_t)r0 * KDIM) : (W_post + (size_t)(r0 - 4) * KDIM);
        wrowp[1] = W_res + (size_t)(r0)     * KDIM;  // rows 8..15  -> res 0..7
        wrowp[2] = W_res + (size_t)(r0 + 8) * KDIM;  // rows 16..23 -> res 8..15
    }

    const float* xbase = x + (size_t)tokbase * KDIM;

    float acc[3][4];
    #pragma unroll
    for (int n = 0; n < 3; n++)
        #pragma unroll
        for (int j = 0; j < 4; j++) acc[n][j] = 0.f;

    // ---- prologue: issue stages 0..NBUF-2 into bufs 0..NBUF-2 ----
    #pragma unroll
    for (int ps = 0; ps < NBUF - 1; ps++) {
        const int kb = ps * KSTAGE;
        float* xbuf = xs + ps * XS_FLOATS;     // compile-time offset
        float* wbuf = ws + ps * WS_FLOATS;
        #pragma unroll
        for (int i = 0; i < 8; i++) {
            int tok = stok + i * 8;
            cp_async16(&xbuf[tok * XSTRIDE + c4], xbase + (size_t)tok * KDIM + kb + c4);
        }
        #pragma unroll
        for (int i = 0; i < 3; i++) {
            int row = (tid >> 4) + i * 8;
            cp_async16(&wbuf[row * WSTRIDE + c4], wrowp[i] + kb + c4);
        }
        asm volatile("cp.async.commit_group;\n");
    }

    // ---- main loop: outer runtime loop x inner unrolled-by-NBUF so every
    //      smem buffer index is a compile-time constant (R3 regression fix) ----
    #pragma unroll 1
    for (int sb = 0; sb < NSTAGES / NBUF; sb++) {
        #pragma unroll
        for (int b = 0; b < NBUF; b++) {
            const int s = sb * NBUF + b;
            if (s + NBUF - 1 < NSTAGES) {
                const int kb = (s + NBUF - 1) * KSTAGE;
                const int nb = (b + NBUF - 1) & (NBUF - 1);   // compile-time
                float* xbuf = xs + nb * XS_FLOATS;
                float* wbuf = ws + nb * WS_FLOATS;
                #pragma unroll
                for (int i = 0; i < 8; i++) {
                    int tok = stok + i * 8;
                    cp_async16(&xbuf[tok * XSTRIDE + c4],
                               xbase + (size_t)tok * KDIM + kb + c4);
                }
                #pragma unroll
                for (int i = 0; i < 3; i++) {
                    int row = (tid >> 4) + i * 8;
                    cp_async16(&wbuf[row * WSTRIDE + c4], wrowp[i] + kb + c4);
                }
                asm volatile("cp.async.commit_group;\n");
                asm volatile("cp.async.wait_group %0;\n" :: "n"(NBUF - 1));
            } else {
                asm volatile("cp.async.wait_group 0;\n");
            }
            __syncthreads();

            // compute on buf = b  (compile-time constant offsets)
            const float* xr0 = xs + b * XS_FLOATS + (warp * 16 + g) * XSTRIDE + tig;
            const float* xr1 = xr0 + 8 * XSTRIDE;
            const float* wr  = ws + b * WS_FLOATS + g * WSTRIDE + tig;

            #pragma unroll
            for (int st = 0; st < KSTAGE / 8; st++) {
                unsigned a0 = __float_as_uint(xr0[st * 8]);
                unsigned a2 = __float_as_uint(xr0[st * 8 + 4]);
                unsigned a1 = __float_as_uint(xr1[st * 8]);
                unsigned a3 = __float_as_uint(xr1[st * 8 + 4]);
                #pragma unroll
                for (int nt = 0; nt < 3; nt++) {
                    unsigned b0 = __float_as_uint(wr[nt * 8 * WSTRIDE + st * 8]);
                    unsigned b1 = __float_as_uint(wr[nt * 8 * WSTRIDE + st * 8 + 4]);
                    mma_tf32(acc[nt], a0, a1, a2, a3, b0, b1);
                }
            }
            __syncthreads();
        }
    }

    // ---- epilogue: gather 24 outputs per token into smem, then per-token math ----
    float* accs = smem;   // 64 * 25 floats, reuse staging buffer
    {
        int t0 = warp * 16 + g;
        #pragma unroll
        for (int nt = 0; nt < 3; nt++) {
            int n0 = nt * 8 + tig * 2;
            accs[t0 * 25 + n0]           = acc[nt][0];
            accs[t0 * 25 + n0 + 1]       = acc[nt][1];
            accs[(t0 + 8) * 25 + n0]     = acc[nt][2];
            accs[(t0 + 8) * 25 + n0 + 1] = acc[nt][3];
        }
    }
    __syncthreads();

    if (tid < MTILE) {
        const float ap  = *a_pre_p;
        const float apo = *a_post_p;
        const float ar  = *a_res_p;
        const int gtok = tokbase + tid;

        float h[NOUT];
        #pragma unroll
        for (int o = 0; o < NOUT; o++) h[o] = accs[tid * 25 + o];

        float* out_pre  = out;
        float* out_post = out + (size_t)TOKENS * 4;
        float* out_res  = out + (size_t)TOKENS * 8;

        #pragma unroll
        for (int o = 0; o < 4; o++) {
            float z = ap * h[o] + b_pre[o];
            out_pre[(size_t)gtok * 4 + o] = 1.f / (1.f + __expf(-z));
        }
        #pragma unroll
        for (int o = 0; o < 4; o++) {
            float z = apo * h[4 + o] + b_post[o];
            out_post[(size_t)gtok * 4 + o] = 2.f / (1.f + __expf(-z));
        }

        // Sinkhorn-Knopp, linear domain (== log-domain reference in exact arithmetic)
        float P[16];
        #pragma unroll
        for (int i = 0; i < 16; i++) P[i] = __expf(ar * h[8 + i] + b_res[i]);

        #pragma unroll 1
        for (int it = 0; it < 20; it++) {
            #pragma unroll
            for (int i = 0; i < 4; i++) {
                float srow = P[i*4] + P[i*4+1] + P[i*4+2] + P[i*4+3];
                float r = 1.f / srow;
                P[i*4] *= r; P[i*4+1] *= r; P[i*4+2] *= r; P[i*4+3] *= r;
            }
            #pragma unroll
            for (int j = 0; j < 4; j++) {
                float scol = P[j] + P[4+j] + P[8+j] + P[12+j];
                float r = 1.f / scol;
                P[j] *= r; P[4+j] *= r; P[8+j] *= r; P[12+j] *= r;
            }
        }
        #pragma unroll
        for (int i = 0; i < 16; i++) out_res[(size_t)gtok * 16 + i] = P[i];
    }
}

extern "C" void kernel_launch(void* const* d_in, const int* in_sizes, int n_in,
                              void* d_out, int out_size) {
    const float* x      = (const float*)d_in[0];
    const float* a_pre  = (const float*)d_in[1];
    const float* a_post = (const float*)d_in[2];
    const float* a_res  = (const float*)d_in[3];
    const float* b_pre  = (const float*)d_in[4];
    const float* b_post = (const float*)d_in[5];
    const float* b_res  = (const float*)d_in[6];
    const float* W_pre  = (const float*)d_in[7];
    const float* W_post = (const float*)d_in[8];
    const float* W_res  = (const float*)d_in[9];

    cudaFuncSetAttribute(mhc_kernel, cudaFuncAttributeMaxDynamicSharedMemorySize,
                         SMEM_BYTES);

    mhc_kernel<<<TOKENS / MTILE, NTHREADS, SMEM_BYTES>>>(
        x, a_pre, a_post, a_res, b_pre, b_post, b_res,
        W_pre, W_post, W_res, (float*)d_out);
}

// round 5
// speedup vs baseline: 1.4664x; 1.3462x over previous
#include <cuda_runtime.h>
#include <cuda.h>

#define TOKENS   16384
#define KDIM     8192
#define MTILE    64
#define NTHREADS 128
#define KSTAGE   64
#define NSTAGES  (KDIM / KSTAGE)   /* 128 */
#define NBUF     4
#define NOUT     24
#define WSTRIDE  68                /* floats; conflict-free B reads */

/* x buffer: per stage 2 boxes of (64 rows x 32 floats) = 4096 floats (16KB), SW128 swizzled */
#define XBOX_FLOATS   2048                     /* one box: 64*32 */
#define XS_FLOATS     (2 * XBOX_FLOATS)        /* 4096 per buffer */
#define WS_FLOATS     (NOUT * WSTRIDE)         /* 1632 per buffer */
#define XS_TOTAL      (NBUF * XS_FLOATS)       /* 16384 floats = 64KB */
#define WS_TOTAL      (NBUF * WS_FLOATS)       /* 6528 floats  = 26112B */
#define MBAR_OFF_B    ((XS_TOTAL + WS_TOTAL) * 4)          /* 91648 */
#define SMEM_BYTES    (MBAR_OFF_B + 64)

__device__ __forceinline__ void mma_tf32(float c[4],
                                         float a0, float a1, float a2, float a3,
                                         float b0, float b1) {
    asm volatile(
        "mma.sync.aligned.m16n8k8.row.col.f32.tf32.tf32.f32 "
        "{%0,%1,%2,%3}, {%4,%5,%6,%7}, {%8,%9}, {%0,%1,%2,%3};\n"
        : "+f"(c[0]), "+f"(c[1]), "+f"(c[2]), "+f"(c[3])
        : "r"(__float_as_uint(a0)), "r"(__float_as_uint(a1)),
          "r"(__float_as_uint(a2)), "r"(__float_as_uint(a3)),
          "r"(__float_as_uint(b0)), "r"(__float_as_uint(b1)));
}

__device__ __forceinline__ void cp_async16(void* smem_dst, const void* gsrc) {
    unsigned dst = (unsigned)__cvta_generic_to_shared(smem_dst);
    asm volatile("cp.async.cg.shared.global [%0], [%1], 16;\n" :: "r"(dst), "l"(gsrc));
}

__device__ __forceinline__ void tma_2d(unsigned sdst, const CUtensorMap* map,
                                       int cx, int cy, unsigned mbar) {
    asm volatile(
        "cp.async.bulk.tensor.2d.shared::cta.global.tile.mbarrier::complete_tx::bytes "
        "[%0], [%1, {%2, %3}], [%4];\n"
        :: "r"(sdst), "l"(map), "r"(cx), "r"(cy), "r"(mbar) : "memory");
}

__device__ __forceinline__ void mbar_wait(unsigned mbar, unsigned parity) {
    unsigned done;
    do {
        asm volatile(
            "{\n\t.reg .pred p;\n\t"
            "mbarrier.try_wait.parity.acquire.cta.shared::cta.b64 p, [%1], %2;\n\t"
            "selp.b32 %0, 1, 0, p;\n\t}"
            : "=r"(done) : "r"(mbar), "r"(parity) : "memory");
    } while (!done);
}

__global__ void __launch_bounds__(NTHREADS)
mhc_kernel(const __grid_constant__ CUtensorMap xmap,
           const float* __restrict__ a_pre_p, const float* __restrict__ a_post_p,
           const float* __restrict__ a_res_p,
           const float* __restrict__ b_pre, const float* __restrict__ b_post,
           const float* __restrict__ b_res,
           const float* __restrict__ W_pre, const float* __restrict__ W_post,
           const float* __restrict__ W_res,
           float* __restrict__ out)
{
    extern __shared__ float smem[];
    float* xs = smem;                  // NBUF * XS_FLOATS (16KB-aligned buffers)
    float* ws = smem + XS_TOTAL;       // NBUF * WS_FLOATS

    const int tid  = threadIdx.x;
    const int lane = tid & 31;
    const int warp = tid >> 5;
    const int g    = lane >> 2;
    const int tig  = lane & 3;
    const int tokbase = blockIdx.x * MTILE;

    const unsigned mbar0 = (unsigned)__cvta_generic_to_shared((char*)smem + MBAR_OFF_B);

    // mbarrier init
    if (tid == 0) {
        #pragma unroll
        for (int i = 0; i < NBUF; i++)
            asm volatile("mbarrier.init.shared.b64 [%0], 1;\n" :: "r"(mbar0 + i * 8) : "memory");
    }
    __syncthreads();

    // ---- W staging assignment (cp.async) ----
    const int c4 = (tid & 15) * 4;
    const float* wrowp[3];
    {
        int r0 = tid >> 4;
        wrowp[0] = (r0 < 4) ? (W_pre + (size_t)r0 * KDIM) : (W_post + (size_t)(r0 - 4) * KDIM);
        wrowp[1] = W_res + (size_t)(r0)     * KDIM;
        wrowp[2] = W_res + (size_t)(r0 + 8) * KDIM;
    }

    float acc[3][4];
    #pragma unroll
    for (int n = 0; n < 3; n++)
        #pragma unroll
        for (int j = 0; j < 4; j++) acc[n][j] = 0.f;

    // fragment-load constants (SW128: physical chunk = logical ^ (row&7))
    const int row_lo = warp * 16 + g;                 // token row within tile
    const int cA0 = ((2 * tig)     ^ g) * 4;          // float offset of 16B chunk, h=0
    const int cA1 = ((2 * tig + 1) ^ g) * 4;          // h=1

    // ---- prologue: stages 0..NBUF-2 ----
    #pragma unroll
    for (int ps = 0; ps < NBUF - 1; ps++) {
        const int kb = ps * KSTAGE;
        float* wbuf = ws + ps * WS_FLOATS;
        #pragma unroll
        for (int i = 0; i < 3; i++) {
            int row = (tid >> 4) + i * 8;
            cp_async16(&wbuf[row * WSTRIDE + c4], wrowp[i] + kb + c4);
        }
        asm volatile("cp.async.commit_group;\n");
        if (tid == 0) {
            unsigned mb = mbar0 + ps * 8;
            asm volatile("mbarrier.arrive.expect_tx.shared.b64 _, [%0], %1;\n"
                         :: "r"(mb), "r"(16384u) : "memory");
            unsigned d0 = (unsigned)__cvta_generic_to_shared(xs + ps * XS_FLOATS);
            tma_2d(d0,                    &xmap, kb,      tokbase, mb);
            tma_2d(d0 + XBOX_FLOATS * 4,  &xmap, kb + 32, tokbase, mb);
        }
    }

    // ---- main loop: compile-time buffer indices ----
    #pragma unroll 1
    for (int sb = 0; sb < NSTAGES / NBUF; sb++) {
        const unsigned parity = (unsigned)(sb & 1);
        #pragma unroll
        for (int b = 0; b < NBUF; b++) {
            const int s = sb * NBUF + b;
            if (s + NBUF - 1 < NSTAGES) {
                const int kb = (s + NBUF - 1) * KSTAGE;
                const int nb = (b + NBUF - 1) & (NBUF - 1);   // compile-time
                float* wbuf = ws + nb * WS_FLOATS;
                #pragma unroll
                for (int i = 0; i < 3; i++) {
                    int row = (tid >> 4) + i * 8;
                    cp_async16(&wbuf[row * WSTRIDE + c4], wrowp[i] + kb + c4);
                }
                asm volatile("cp.async.commit_group;\n");
                asm volatile("cp.async.wait_group %0;\n" :: "n"(NBUF - 1));
                if (tid == 0) {
                    unsigned mb = mbar0 + nb * 8;
                    asm volatile("mbarrier.arrive.expect_tx.shared.b64 _, [%0], %1;\n"
                                 :: "r"(mb), "r"(16384u) : "memory");
                    unsigned d0 = (unsigned)__cvta_generic_to_shared(xs + nb * XS_FLOATS);
                    tma_2d(d0,                   &xmap, kb,      tokbase, mb);
                    tma_2d(d0 + XBOX_FLOATS * 4, &xmap, kb + 32, tokbase, mb);
                }
            } else {
                asm volatile("cp.async.wait_group 0;\n");
            }
            mbar_wait(mbar0 + b * 8, parity);
            __syncthreads();

            const float* xb = xs + b * XS_FLOATS;
            const float* wb = ws + b * WS_FLOATS;

            #pragma unroll
            for (int bbox = 0; bbox < 2; bbox++) {
                const float* xbb = xb + bbox * XBOX_FLOATS;
                #pragma unroll
                for (int h = 0; h < 2; h++) {
                    const int cA = h ? cA1 : cA0;
                    float4 alo = *(const float4*)(xbb + row_lo * 32 + cA);
                    float4 ahi = *(const float4*)(xbb + (row_lo + 8) * 32 + cA);
                    #pragma unroll
                    for (int nt = 0; nt < 3; nt++) {
                        float4 w4 = *(const float4*)(wb + (nt * 8 + g) * WSTRIDE
                                                        + bbox * 32 + tig * 8 + h * 4);
                        mma_tf32(acc[nt], alo.x, ahi.x, alo.y, ahi.y, w4.x, w4.y);
                        mma_tf32(acc[nt], alo.z, ahi.z, alo.w, ahi.w, w4.z, w4.w);
                    }
                }
            }
            __syncthreads();
        }
    }

    // ---- epilogue ----
    float* accs = smem;   // 64 * 25 floats, reuse staging buffer
    {
        int t0 = warp * 16 + g;
        #pragma unroll
        for (int nt = 0; nt < 3; nt++) {
            int n0 = nt * 8 + tig * 2;
            accs[t0 * 25 + n0]           = acc[nt][0];
            accs[t0 * 25 + n0 + 1]       = acc[nt][1];
            accs[(t0 + 8) * 25 + n0]     = acc[nt][2];
            accs[(t0 + 8) * 25 + n0 + 1] = acc[nt][3];
        }
    }
    __syncthreads();

    if (tid < MTILE) {
        const float ap  = *a_pre_p;
        const float apo = *a_post_p;
        const float ar  = *a_res_p;
        const int gtok = tokbase + tid;

        float h[NOUT];
        #pragma unroll
        for (int o = 0; o < NOUT; o++) h[o] = accs[tid * 25 + o];

        float* out_pre  = out;
        float* out_post = out + (size_t)TOKENS * 4;
        float* out_res  = out + (size_t)TOKENS * 8;

        #pragma unroll
        for (int o = 0; o < 4; o++) {
            float z = ap * h[o] + b_pre[o];
            out_pre[(size_t)gtok * 4 + o] = 1.f / (1.f + __expf(-z));
        }
        #pragma unroll
        for (int o = 0; o < 4; o++) {
            float z = apo * h[4 + o] + b_post[o];
            out_post[(size_t)gtok * 4 + o] = 2.f / (1.f + __expf(-z));
        }

        float P[16];
        #pragma unroll
        for (int i = 0; i < 16; i++) P[i] = __expf(ar * h[8 + i] + b_res[i]);

        #pragma unroll 1
        for (int it = 0; it < 20; it++) {
            #pragma unroll
            for (int i = 0; i < 4; i++) {
                float srow = P[i*4] + P[i*4+1] + P[i*4+2] + P[i*4+3];
                float r = 1.f / srow;
                P[i*4] *= r; P[i*4+1] *= r; P[i*4+2] *= r; P[i*4+3] *= r;
            }
            #pragma unroll
            for (int j = 0; j < 4; j++) {
                float scol = P[j] + P[4+j] + P[8+j] + P[12+j];
                float r = 1.f / scol;
                P[j] *= r; P[4+j] *= r; P[8+j] *= r; P[12+j] *= r;
            }
        }
        #pragma unroll
        for (int i = 0; i < 16; i++) out_res[(size_t)gtok * 16 + i] = P[i];
    }
}

typedef CUresult (*tmap_encode_fn)(
    CUtensorMap*, CUtensorMapDataType, cuuint32_t, void*,
    const cuuint64_t*, const cuuint64_t*, const cuuint32_t*, const cuuint32_t*,
    CUtensorMapInterleave, CUtensorMapSwizzle, CUtensorMapL2promotion,
    CUtensorMapFloatOOBfill);

extern "C" void kernel_launch(void* const* d_in, const int* in_sizes, int n_in,
                              void* d_out, int out_size) {
    const float* x      = (const float*)d_in[0];
    const float* a_pre  = (const float*)d_in[1];
    const float* a_post = (const float*)d_in[2];
    const float* a_res  = (const float*)d_in[3];
    const float* b_pre  = (const float*)d_in[4];
    const float* b_post = (const float*)d_in[5];
    const float* b_res  = (const float*)d_in[6];
    const float* W_pre  = (const float*)d_in[7];
    const float* W_post = (const float*)d_in[8];
    const float* W_res  = (const float*)d_in[9];

    // Driver entry point without -lcuda
    void* fnp = nullptr;
    cudaDriverEntryPointQueryResult qr;
    cudaGetDriverEntryPointByVersion("cuTensorMapEncodeTiled", &fnp, 12000,
                                     cudaEnableDefault, &qr);
    tmap_encode_fn encode = (tmap_encode_fn)fnp;

    CUtensorMap xmap;
    cuuint64_t dims[2]    = {KDIM, TOKENS};
    cuuint64_t strides[1] = {(cuuint64_t)KDIM * 4};
    cuuint32_t box[2]     = {32, MTILE};
    cuuint32_t estr[2]    = {1, 1};
    encode(&xmap, CU_TENSOR_MAP_DATA_TYPE_FLOAT32, 2, (void*)x,
           dims, strides, box, estr,
           CU_TENSOR_MAP_INTERLEAVE_NONE, CU_TENSOR_MAP_SWIZZLE_128B,
           CU_TENSOR_MAP_L2_PROMOTION_L2_128B, CU_TENSOR_MAP_FLOAT_OOB_FILL_NONE);

    cudaFuncSetAttribute(mhc_kernel, cudaFuncAttributeMaxDynamicSharedMemorySize,
                         SMEM_BYTES);

    mhc_kernel<<<TOKENS / MTILE, NTHREADS, SMEM_BYTES>>>(
        xmap, a_pre, a_post, a_res, b_pre, b_post, b_res,
        W_pre, W_post, W_res, (float*)d_out);
}

// round 6
// speedup vs baseline: 1.4815x; 1.0103x over previous
#include <cuda_runtime.h>
#include <cuda.h>

#define TOKENS   16384
#define KDIM     8192
#define MTILE    64
#define NTHREADS 128
#define KSTAGE   64
#define NSTAGES  (KDIM / KSTAGE)   /* 128 */
#define NBUF     4
#define NOUT     24
#define WSTRIDE  68                /* floats; conflict-free B reads */

/* x buffer: per stage 2 boxes of (64 rows x 32 floats) = 4096 floats (16KB), SW128 swizzled */
#define XBOX_FLOATS   2048                     /* one box: 64*32 */
#define XS_FLOATS     (2 * XBOX_FLOATS)        /* 4096 per buffer */
#define WS_FLOATS     (NOUT * WSTRIDE)         /* 1632 per buffer */
#define XS_TOTAL      (NBUF * XS_FLOATS)       /* 16384 floats = 64KB */
#define WS_TOTAL      (NBUF * WS_FLOATS)       /* 6528 floats  = 26112B */
#define MBAR_OFF_B    ((XS_TOTAL + WS_TOTAL) * 4)          /* 91648 */
#define SMEM_BYTES    (MBAR_OFF_B + 64)

__device__ __forceinline__ void mma_tf32(float c[4],
                                         float a0, float a1, float a2, float a3,
                                         float b0, float b1) {
    asm volatile(
        "mma.sync.aligned.m16n8k8.row.col.f32.tf32.tf32.f32 "
        "{%0,%1,%2,%3}, {%4,%5,%6,%7}, {%8,%9}, {%0,%1,%2,%3};\n"
        : "+f"(c[0]), "+f"(c[1]), "+f"(c[2]), "+f"(c[3])
        : "r"(__float_as_uint(a0)), "r"(__float_as_uint(a1)),
          "r"(__float_as_uint(a2)), "r"(__float_as_uint(a3)),
          "r"(__float_as_uint(b0)), "r"(__float_as_uint(b1)));
}

__device__ __forceinline__ void cp_async16(void* smem_dst, const void* gsrc) {
    unsigned dst = (unsigned)__cvta_generic_to_shared(smem_dst);
    asm volatile("cp.async.cg.shared.global [%0], [%1], 16;\n" :: "r"(dst), "l"(gsrc));
}

__device__ __forceinline__ void tma_2d(unsigned sdst, const CUtensorMap* map,
                                       int cx, int cy, unsigned mbar) {
    asm volatile(
        "cp.async.bulk.tensor.2d.shared::cta.global.tile.mbarrier::complete_tx::bytes "
        "[%0], [%1, {%2, %3}], [%4];\n"
        :: "r"(sdst), "l"(map), "r"(cx), "r"(cy), "r"(mbar) : "memory");
}

__device__ __forceinline__ void mbar_wait(unsigned mbar, unsigned parity) {
    unsigned done;
    do {
        asm volatile(
            "{\n\t.reg .pred p;\n\t"
            "mbarrier.try_wait.parity.acquire.cta.shared::cta.b64 p, [%1], %2;\n\t"
            "selp.b32 %0, 1, 0, p;\n\t}"
            : "=r"(done) : "r"(mbar), "r"(parity) : "memory");
    } while (!done);
}

__global__ void __launch_bounds__(NTHREADS)
mhc_kernel(const __grid_constant__ CUtensorMap xmap,
           const float* __restrict__ a_pre_p, const float* __restrict__ a_post_p,
           const float* __restrict__ a_res_p,
           const float* __restrict__ b_pre, const float* __restrict__ b_post,
           const float* __restrict__ b_res,
           const float* __restrict__ W_pre, const float* __restrict__ W_post,
           const float* __restrict__ W_res,
           float* __restrict__ out)
{
    extern __shared__ float smem[];
    float* xs = smem;                  // NBUF * XS_FLOATS
    float* ws = smem + XS_TOTAL;       // NBUF * WS_FLOATS

    const int tid  = threadIdx.x;
    const int lane = tid & 31;
    const int warp = tid >> 5;
    const int g    = lane >> 2;
    const int tig  = lane & 3;
    const int tokbase = blockIdx.x * MTILE;

    const unsigned mbar0 = (unsigned)__cvta_generic_to_shared((char*)smem + MBAR_OFF_B);

    if (tid == 0) {
        #pragma unroll
        for (int i = 0; i < NBUF; i++)
            asm volatile("mbarrier.init.shared.b64 [%0], 1;\n" :: "r"(mbar0 + i * 8) : "memory");
    }
    __syncthreads();

    // ---- W staging assignment (cp.async) ----
    const int c4 = (tid & 15) * 4;
    const float* wrowp[3];
    {
        int r0 = tid >> 4;
        wrowp[0] = (r0 < 4) ? (W_pre + (size_t)r0 * KDIM) : (W_post + (size_t)(r0 - 4) * KDIM);
        wrowp[1] = W_res + (size_t)(r0)     * KDIM;
        wrowp[2] = W_res + (size_t)(r0 + 8) * KDIM;
    }

    float acc[3][4];
    #pragma unroll
    for (int n = 0; n < 3; n++)
        #pragma unroll
        for (int j = 0; j < 4; j++) acc[n][j] = 0.f;

    // fragment-load constants (SW128: physical chunk = logical ^ (row&7))
    const int row_lo = warp * 16 + g;
    const int cA0 = ((2 * tig)     ^ g) * 4;
    const int cA1 = ((2 * tig + 1) ^ g) * 4;

    // ---- prologue: stages 0..NBUF-2 ----
    #pragma unroll
    for (int ps = 0; ps < NBUF - 1; ps++) {
        const int kb = ps * KSTAGE;
        float* wbuf = ws + ps * WS_FLOATS;
        #pragma unroll
        for (int i = 0; i < 3; i++) {
            int row = (tid >> 4) + i * 8;
            cp_async16(&wbuf[row * WSTRIDE + c4], wrowp[i] + kb + c4);
        }
        asm volatile("cp.async.commit_group;\n");
        if (tid == 0) {
            unsigned mb = mbar0 + ps * 8;
            asm volatile("mbarrier.arrive.expect_tx.shared.b64 _, [%0], %1;\n"
                         :: "r"(mb), "r"(16384u) : "memory");
            unsigned d0 = (unsigned)__cvta_generic_to_shared(xs + ps * XS_FLOATS);
            tma_2d(d0,                    &xmap, kb,      tokbase, mb);
            tma_2d(d0 + XBOX_FLOATS * 4,  &xmap, kb + 32, tokbase, mb);
        }
    }

    // ---- main loop: ONE barrier per stage ----
    // Order per stage s (buffer b = s mod 4):
    //   mbar_wait(full[b])            : x for stage s present (per-thread acquire)
    //   cp.async.wait_group NBUF-2    : own W copies for stage s complete
    //   __syncthreads()               : publish W; prove all warps done compute(s-1)
    //   issue stage s+3 into buffer b-1 (buffer of stage s-1; safe by the sync)
    //   compute(b)
    // Tail stages commit an empty group so wait_group accounting stays uniform.
    #pragma unroll 1
    for (int sb = 0; sb < NSTAGES / NBUF; sb++) {
        const unsigned parity = (unsigned)(sb & 1);
        #pragma unroll
        for (int b = 0; b < NBUF; b++) {
            const int s = sb * NBUF + b;

            mbar_wait(mbar0 + b * 8, parity);
            asm volatile("cp.async.wait_group %0;\n" :: "n"(NBUF - 2));
            __syncthreads();

            if (s + NBUF - 1 < NSTAGES) {
                const int kb = (s + NBUF - 1) * KSTAGE;
                const int nb = (b + NBUF - 1) & (NBUF - 1);   // compile-time
                float* wbuf = ws + nb * WS_FLOATS;
                #pragma unroll
                for (int i = 0; i < 3; i++) {
                    int row = (tid >> 4) + i * 8;
                    cp_async16(&wbuf[row * WSTRIDE + c4], wrowp[i] + kb + c4);
                }
                asm volatile("cp.async.commit_group;\n");
                if (tid == 0) {
                    unsigned mb = mbar0 + nb * 8;
                    asm volatile("mbarrier.arrive.expect_tx.shared.b64 _, [%0], %1;\n"
                                 :: "r"(mb), "r"(16384u) : "memory");
                    unsigned d0 = (unsigned)__cvta_generic_to_shared(xs + nb * XS_FLOATS);
                    tma_2d(d0,                   &xmap, kb,      tokbase, mb);
                    tma_2d(d0 + XBOX_FLOATS * 4, &xmap, kb + 32, tokbase, mb);
                }
            } else {
                asm volatile("cp.async.commit_group;\n");   // empty group: keep ledger uniform
            }

            const float* xb = xs + b * XS_FLOATS;
            const float* wb = ws + b * WS_FLOATS;

            #pragma unroll
            for (int bbox = 0; bbox < 2; bbox++) {
                const float* xbb = xb + bbox * XBOX_FLOATS;
                #pragma unroll
                for (int h = 0; h < 2; h++) {
                    const int cA = h ? cA1 : cA0;
                    float4 alo = *(const float4*)(xbb + row_lo * 32 + cA);
                    float4 ahi = *(const float4*)(xbb + (row_lo + 8) * 32 + cA);
                    #pragma unroll
                    for (int nt = 0; nt < 3; nt++) {
                        float4 w4 = *(const float4*)(wb + (nt * 8 + g) * WSTRIDE
                                                        + bbox * 32 + tig * 8 + h * 4);
                        mma_tf32(acc[nt], alo.x, ahi.x, alo.y, ahi.y, w4.x, w4.y);
                        mma_tf32(acc[nt], alo.z, ahi.z, alo.w, ahi.w, w4.z, w4.w);
                    }
                }
            }
        }
    }

    // ---- epilogue ----
    // accs lives in xs buffer 0 region; last compute used buffer 3 — disjoint,
    // and the per-stage syncs bound warp skew to one stage, so no hazard.
    float* accs = smem;   // 64 * 25 floats
    {
        int t0 = warp * 16 + g;
        #pragma unroll
        for (int nt = 0; nt < 3; nt++) {
            int n0 = nt * 8 + tig * 2;
            accs[t0 * 25 + n0]           = acc[nt][0];
            accs[t0 * 25 + n0 + 1]       = acc[nt][1];
            accs[(t0 + 8) * 25 + n0]     = acc[nt][2];
            accs[(t0 + 8) * 25 + n0 + 1] = acc[nt][3];
        }
    }
    __syncthreads();

    if (tid < MTILE) {
        const float ap  = *a_pre_p;
        const float apo = *a_post_p;
        const float ar  = *a_res_p;
        const int gtok = tokbase + tid;

        float h[NOUT];
        #pragma unroll
        for (int o = 0; o < NOUT; o++) h[o] = accs[tid * 25 + o];

        float* out_pre  = out;
        float* out_post = out + (size_t)TOKENS * 4;
        float* out_res  = out + (size_t)TOKENS * 8;

        #pragma unroll
        for (int o = 0; o < 4; o++) {
            float z = ap * h[o] + b_pre[o];
            out_pre[(size_t)gtok * 4 + o] = 1.f / (1.f + __expf(-z));
        }
        #pragma unroll
        for (int o = 0; o < 4; o++) {
            float z = apo * h[4 + o] + b_post[o];
            out_post[(size_t)gtok * 4 + o] = 2.f / (1.f + __expf(-z));
        }

        float P[16];
        #pragma unroll
        for (int i = 0; i < 16; i++) P[i] = __expf(ar * h[8 + i] + b_res[i]);

        #pragma unroll 1
        for (int it = 0; it < 20; it++) {
            #pragma unroll
            for (int i = 0; i < 4; i++) {
                float srow = P[i*4] + P[i*4+1] + P[i*4+2] + P[i*4+3];
                float r = 1.f / srow;
                P[i*4] *= r; P[i*4+1] *= r; P[i*4+2] *= r; P[i*4+3] *= r;
            }
            #pragma unroll
            for (int j = 0; j < 4; j++) {
                float scol = P[j] + P[4+j] + P[8+j] + P[12+j];
                float r = 1.f / scol;
                P[j] *= r; P[4+j] *= r; P[8+j] *= r; P[12+j] *= r;
            }
        }
        #pragma unroll
        for (int i = 0; i < 16; i++) out_res[(size_t)gtok * 16 + i] = P[i];
    }
}

typedef CUresult (*tmap_encode_fn)(
    CUtensorMap*, CUtensorMapDataType, cuuint32_t, void*,
    const cuuint64_t*, const cuuint64_t*, const cuuint32_t*, const cuuint32_t*,
    CUtensorMapInterleave, CUtensorMapSwizzle, CUtensorMapL2promotion,
    CUtensorMapFloatOOBfill);

extern "C" void kernel_launch(void* const* d_in, const int* in_sizes, int n_in,
                              void* d_out, int out_size) {
    const float* x      = (const float*)d_in[0];
    const float* a_pre  = (const float*)d_in[1];
    const float* a_post = (const float*)d_in[2];
    const float* a_res  = (const float*)d_in[3];
    const float* b_pre  = (const float*)d_in[4];
    const float* b_post = (const float*)d_in[5];
    const float* b_res  = (const float*)d_in[6];
    const float* W_pre  = (const float*)d_in[7];
    const float* W_post = (const float*)d_in[8];
    const float* W_res  = (const float*)d_in[9];

    void* fnp = nullptr;
    cudaDriverEntryPointQueryResult qr;
    cudaGetDriverEntryPointByVersion("cuTensorMapEncodeTiled", &fnp, 12000,
                                     cudaEnableDefault, &qr);
    tmap_encode_fn encode = (tmap_encode_fn)fnp;

    CUtensorMap xmap;
    cuuint64_t dims[2]    = {KDIM, TOKENS};
    cuuint64_t strides[1] = {(cuuint64_t)KDIM * 4};
    cuuint32_t box[2]     = {32, MTILE};
    cuuint32_t estr[2]    = {1, 1};
    encode(&xmap, CU_TENSOR_MAP_DATA_TYPE_FLOAT32, 2, (void*)x,
           dims, strides, box, estr,
           CU_TENSOR_MAP_INTERLEAVE_NONE, CU_TENSOR_MAP_SWIZZLE_128B,
           CU_TENSOR_MAP_L2_PROMOTION_L2_128B, CU_TENSOR_MAP_FLOAT_OOB_FILL_NONE);

    cudaFuncSetAttribute(mhc_kernel, cudaFuncAttributeMaxDynamicSharedMemorySize,
                         SMEM_BYTES);

    mhc_kernel<<<TOKENS / MTILE, NTHREADS, SMEM_BYTES>>>(
        xmap, a_pre, a_post, a_res, b_pre, b_post, b_res,
        W_pre, W_post, W_res, (float*)d_out);
}